// round 13
// baseline (speedup 1.0000x reference)
#include <cuda_runtime.h>
#include <cuda_bf16.h>
#include <math.h>
#include <stdint.h>

#define NN 10000
#define NE 160000
#define DI 128
#define DE 512
#define DH 256

// ---------------- scratch (device globals; no allocation allowed) ----------
__device__ __align__(16) float g_xlr[NN * 2 * DE];   // [node][xl(512) | xr(512)]
__device__ int   g_src[NE];
__device__ int   g_dst[NE];
__device__ int   g_deg[NN];
__device__ int   g_rs[NN + 1];
__device__ int   g_cur[NN];
__device__ int   g_csrc[NE];
__device__ __align__(16) float g_m1[NN * DH];
__device__ __align__(16) float g_m2[NN * DH];
__device__ float g_logit[NN];
__device__ int   g_is64;
__device__ __align__(16) __nv_bfloat16 g_ahi[NN * DE];
__device__ __align__(16) __nv_bfloat16 g_alo[NN * DE];
__device__ __align__(16) __nv_bfloat16 g_bhi[NN * DH];   // MLP split output
__device__ __align__(16) __nv_bfloat16 g_blo[NN * DH];
__device__ __align__(16) __nv_bfloat16 g_whi[2 * DE * DE];
__device__ __align__(16) __nv_bfloat16 g_wlo[2 * DE * DE];

// ---------------- edge decode (+ degree histogram fused) --------------------
__global__ void k_detect(const int* __restrict__ w) {
    __shared__ int s;
    if (threadIdx.x == 0) s = 0;
    __syncthreads();
    int acc = 0;
    for (int i = threadIdx.x; i < 2048; i += 256) acc |= w[2 * i + 1];
    atomicOr(&s, acc);
    for (int i = threadIdx.x; i < NN; i += 256) g_deg[i] = 0;
    __syncthreads();
    if (threadIdx.x == 0) g_is64 = (s == 0) ? 1 : 0;
}

__global__ void k_edges(const int* __restrict__ w) {
    int i = blockIdx.x * blockDim.x + threadIdx.x;
    if (i >= NE) return;
    int s, d;
    if (g_is64) { s = w[2 * i]; d = w[2 * (NE + i)]; }
    else        { s = w[i];     d = w[NE + i]; }
    if ((unsigned)s >= NN) s = 0;
    if ((unsigned)d >= NN) d = 0;
    g_src[i] = s;
    g_dst[i] = d;
    atomicAdd(&g_deg[d], 1);
}

// coalesced chunked scan: 10 chunks of 1024, warp-shuffle within chunk
__global__ void k_scan() {
    __shared__ int wsum[32];
    __shared__ int sbase;
    int t = threadIdx.x;
    int lane = t & 31, w = t >> 5;
    if (t == 0) sbase = 0;
    __syncthreads();
    for (int c = 0; c < NN; c += 1024) {
        int idx = c + t;
        int v = (idx < NN) ? g_deg[idx] : 0;
        int inc = v;
        #pragma unroll
        for (int o = 1; o < 32; o <<= 1) {
            int u = __shfl_up_sync(0xffffffffu, inc, o);
            if (lane >= o) inc += u;
        }
        if (lane == 31) wsum[w] = inc;
        __syncthreads();
        if (w == 0) {
            int vv = wsum[lane];
            #pragma unroll
            for (int o = 1; o < 32; o <<= 1) {
                int u = __shfl_up_sync(0xffffffffu, vv, o);
                if (lane >= o) vv += u;
            }
            wsum[lane] = vv;
        }
        __syncthreads();
        int base = sbase + ((w > 0) ? wsum[w - 1] : 0) + inc - v;
        if (idx < NN) { g_rs[idx] = base; g_cur[idx] = base; }
        __syncthreads();
        if (t == 0) sbase += wsum[31];
        __syncthreads();
    }
    if (t == 0) g_rs[NN] = sbase;
}

__global__ void k_scatter() {
    int i = blockIdx.x * blockDim.x + threadIdx.x;
    if (i >= NE) return;
    int pos = atomicAdd(&g_cur[g_dst[i]], 1);
    g_csrc[pos] = g_src[i];
}

// ---------------- hi/lo split (layer-1 input only) ---------------------------
__global__ void k_split(const float* __restrict__ a, __nv_bfloat16* __restrict__ hi,
                        __nv_bfloat16* __restrict__ lo, int n) {
    int i = blockIdx.x * blockDim.x + threadIdx.x;
    if (i >= n) return;
    float v = a[i];
    __nv_bfloat16 h = __float2bfloat16_rn(v);
    hi[i] = h;
    lo[i] = __float2bfloat16_rn(v - __bfloat162float(h));
}

// ---------------- coalesced weight prep: W[K,M] -> WT[m+rofs][K] hi/lo -------
__global__ __launch_bounds__(256) void k_prep_w(
    const float* __restrict__ W, __nv_bfloat16* __restrict__ hiT,
    __nv_bfloat16* __restrict__ loT, int K, int M, int rofs) {
    __shared__ float s[64][33];
    int k0 = blockIdx.x * 64, m0 = blockIdx.y * 32;
    int tid = threadIdx.x;
    #pragma unroll
    for (int i = tid; i < 64 * 32; i += 256) {
        int kk = i >> 5, mm = i & 31;
        s[kk][mm] = W[(size_t)(k0 + kk) * M + m0 + mm];
    }
    __syncthreads();
    #pragma unroll
    for (int i = tid; i < 32 * 32; i += 256) {
        int mm = i >> 5, kp = i & 31;
        float v0 = s[2 * kp][mm], v1 = s[2 * kp + 1][mm];
        __nv_bfloat162 h2 = __floats2bfloat162_rn(v0, v1);
        float l0 = v0 - __bfloat162float(__low2bfloat16(h2));
        float l1 = v1 - __bfloat162float(__high2bfloat16(h2));
        __nv_bfloat162 l2 = __floats2bfloat162_rn(l0, l1);
        size_t ro = (size_t)(m0 + mm + rofs) * K + k0 + 2 * kp;
        *(uint32_t*)(hiT + ro) = *(uint32_t*)&h2;
        *(uint32_t*)(loT + ro) = *(uint32_t*)&l2;
    }
}

// ---------------- cp.async + ldmatrix bf16 GEMM (3-pass hi/lo) --------------
#define TPAD 40
#define TILE_E (128 * TPAD)
#define STAGE_E (4 * TILE_E)
#define SMEM_GEMM (2 * STAGE_E * 2)

__device__ __forceinline__ void cpa16(uint32_t dst, const void* src, int sz) {
    asm volatile("cp.async.cg.shared.global [%0], [%1], 16, %2;"
                 :: "r"(dst), "l"(src), "r"(sz) : "memory");
}
__device__ __forceinline__ void cpa_commit() {
    asm volatile("cp.async.commit_group;" ::: "memory");
}
template<int N> __device__ __forceinline__ void cpa_wait() {
    asm volatile("cp.async.wait_group %0;" :: "n"(N) : "memory");
}
__device__ __forceinline__ void ldsm4(uint32_t* r, uint32_t addr) {
    asm volatile("ldmatrix.sync.aligned.m8n8.x4.shared.b16 {%0,%1,%2,%3}, [%4];"
                 : "=r"(r[0]), "=r"(r[1]), "=r"(r[2]), "=r"(r[3]) : "r"(addr));
}

// mode bit0: bias + leaky(0.1); mode bit1: also write bf16 hi/lo to Hi/Lo[r*M+c]
// NOTE: Hi/Lo must NOT alias Ahi/Alo (cross-CTA RAW race).
__global__ __launch_bounds__(256, 2) void k_gemm_mma(
    const __nv_bfloat16* __restrict__ Ahi, const __nv_bfloat16* __restrict__ Alo,
    const __nv_bfloat16* __restrict__ BhiT, const __nv_bfloat16* __restrict__ BloT,
    float* __restrict__ C, int Nrows, int K, int M,
    const float* __restrict__ bias, int mode,
    __nv_bfloat16* __restrict__ Hi, __nv_bfloat16* __restrict__ Lo)
{
    extern __shared__ __nv_bfloat16 smem[];
    uint32_t sb = (uint32_t)__cvta_generic_to_shared(smem);

    int tid = threadIdx.x;
    int wid = tid >> 5, lane = tid & 31;
    int wm = wid & 1, wn = wid >> 1;
    int row0 = blockIdx.y * 128;
    int col0 = blockIdx.x * 128;
    int mBase = wm * 64, nBase = wn * 32;
    int g = lane >> 2, cw = lane & 3;
    int mat = lane >> 3, r8 = lane & 7;
    int rsel = (mat & 1) * 8 + r8;
    int csel = (mat >> 1) * 8;

    float acc[4][4][4];
    #pragma unroll
    for (int a = 0; a < 4; a++)
        #pragma unroll
        for (int b = 0; b < 4; b++)
            #pragma unroll
            for (int c = 0; c < 4; c++) acc[a][b][c] = 0.f;

    int nk = K / 32;
    int c0 = tid * 2;

    auto prefetch = [&](int ck, int stage) {
        int kofs = ck * 32;
        uint32_t se = (uint32_t)stage * STAGE_E;
        #pragma unroll
        for (int i = 0; i < 2; i++) {
            int c = c0 + i;
            int r = c >> 2, seg = c & 3;
            uint32_t dA = sb + 2 * (se + r * TPAD + seg * 8);
            int gr = row0 + r;
            int szA = (gr < Nrows) ? 16 : 0;
            const __nv_bfloat16* pa = Ahi + (size_t)gr * K + kofs + seg * 8;
            const __nv_bfloat16* pl = Alo + (size_t)gr * K + kofs + seg * 8;
            if (szA == 0) { pa = Ahi; pl = Alo; }
            cpa16(dA, pa, szA);
            cpa16(dA + 2 * TILE_E, pl, szA);
            const __nv_bfloat16* pb = BhiT + (size_t)(col0 + r) * K + kofs + seg * 8;
            const __nv_bfloat16* pq = BloT + (size_t)(col0 + r) * K + kofs + seg * 8;
            cpa16(dA + 2 * (2 * TILE_E), pb, 16);
            cpa16(dA + 2 * (3 * TILE_E), pq, 16);
        }
        cpa_commit();
    };

    prefetch(0, 0);

    for (int ck = 0; ck < nk; ck++) {
        int stage = ck & 1;
        cpa_wait<0>();
        __syncthreads();          // publishes buf[ck]; all warps done reading buf[ck^1]
        if (ck + 1 < nk) prefetch(ck + 1, stage ^ 1);

        uint32_t se = (uint32_t)stage * STAGE_E;
        #pragma unroll
        for (int pass = 0; pass < 3; pass++) {
            uint32_t aoff = se + ((pass == 1) ? TILE_E : 0u);
            uint32_t boff = se + ((pass == 2) ? 3u * TILE_E : 2u * TILE_E);
            #pragma unroll
            for (int ks = 0; ks < 2; ks++) {
                int kw = ks * 16 + csel;
                uint32_t af[4][4];
                #pragma unroll
                for (int mi = 0; mi < 4; mi++)
                    ldsm4(af[mi], sb + 2 * (aoff + (uint32_t)(mBase + mi * 16 + rsel) * TPAD + kw));
                uint32_t bfr[2][4];
                #pragma unroll
                for (int p = 0; p < 2; p++)
                    ldsm4(bfr[p], sb + 2 * (boff + (uint32_t)(nBase + p * 16 + rsel) * TPAD + kw));
                #pragma unroll
                for (int mi = 0; mi < 4; mi++)
                    #pragma unroll
                    for (int ni = 0; ni < 4; ni++) {
                        float* d = acc[mi][ni];
                        uint32_t b0 = bfr[ni >> 1][ni & 1];
                        uint32_t b1 = bfr[ni >> 1][2 + (ni & 1)];
                        asm volatile(
                            "mma.sync.aligned.m16n8k16.row.col.f32.bf16.bf16.f32 "
                            "{%0,%1,%2,%3}, {%4,%5,%6,%7}, {%8,%9}, {%0,%1,%2,%3};"
                            : "+f"(d[0]), "+f"(d[1]), "+f"(d[2]), "+f"(d[3])
                            : "r"(af[mi][0]), "r"(af[mi][1]), "r"(af[mi][2]), "r"(af[mi][3]),
                              "r"(b0), "r"(b1));
                    }
            }
        }
    }

    #pragma unroll
    for (int mi = 0; mi < 4; mi++) {
        int r0 = row0 + mBase + mi * 16 + g;
        #pragma unroll
        for (int ni = 0; ni < 4; ni++) {
            int cc = col0 + nBase + ni * 8 + cw * 2;
            float v0 = acc[mi][ni][0], v1 = acc[mi][ni][1];
            float v2 = acc[mi][ni][2], v3 = acc[mi][ni][3];
            if (mode & 1) {
                float b0 = bias[cc], b1 = bias[cc + 1];
                v0 += b0; v0 = (v0 > 0.f) ? v0 : 0.1f * v0;
                v1 += b1; v1 = (v1 > 0.f) ? v1 : 0.1f * v1;
                v2 += b0; v2 = (v2 > 0.f) ? v2 : 0.1f * v2;
                v3 += b1; v3 = (v3 > 0.f) ? v3 : 0.1f * v3;
            }
            if (r0 < Nrows) {
                *(float2*)(C + (size_t)r0 * M + cc) = make_float2(v0, v1);
                if (mode & 2) {
                    __nv_bfloat162 h2 = __floats2bfloat162_rn(v0, v1);
                    float l0 = v0 - __bfloat162float(__low2bfloat16(h2));
                    float l1 = v1 - __bfloat162float(__high2bfloat16(h2));
                    __nv_bfloat162 l2 = __floats2bfloat162_rn(l0, l1);
                    *(uint32_t*)(Hi + (size_t)r0 * M + cc) = *(uint32_t*)&h2;
                    *(uint32_t*)(Lo + (size_t)r0 * M + cc) = *(uint32_t*)&l2;
                }
            }
            if (r0 + 8 < Nrows) {
                *(float2*)(C + (size_t)(r0 + 8) * M + cc) = make_float2(v2, v3);
                if (mode & 2) {
                    __nv_bfloat162 h2 = __floats2bfloat162_rn(v2, v3);
                    float l0 = v2 - __bfloat162float(__low2bfloat16(h2));
                    float l1 = v3 - __bfloat162float(__high2bfloat16(h2));
                    __nv_bfloat162 l2 = __floats2bfloat162_rn(l0, l1);
                    *(uint32_t*)(Hi + (size_t)(r0 + 8) * M + cc) = *(uint32_t*)&h2;
                    *(uint32_t*)(Lo + (size_t)(r0 + 8) * M + cc) = *(uint32_t*)&l2;
                }
            }
        }
    }
}

// ---------------- fused GATv2 edge kernel: one-pass online softmax ----------
// one warp per dst, 2-edge unrolled: two independent gathers + logit reductions
// in flight, joint max/rescale update. Mathematically identical to sequential.
__global__ __launch_bounds__(256) void k_gat_edge(const float* __restrict__ att,
                                                  const float* __restrict__ bias) {
    int gw = (blockIdx.x * 256 + threadIdx.x) >> 5;
    int lane = threadIdx.x & 31;
    if (gw >= NN) return;
    int d = gw;
    int rs = g_rs[d], re = g_rs[d + 1];

    float4 xr4[4], at4[4];
    const float4* pxr = (const float4*)(g_xlr + (size_t)d * 1024 + 512);
    const float4* pat = (const float4*)att;
    #pragma unroll
    for (int j = 0; j < 4; j++) {
        xr4[j] = pxr[j * 32 + lane];
        at4[j] = pat[j * 32 + lane];
    }

    float m = -3.0e38f;
    float den = 0.f;
    float accf[16];
    #pragma unroll
    for (int j = 0; j < 16; j++) accf[j] = 0.f;

    int e = rs;
    for (; e + 1 < re; e += 2) {
        int s0 = g_csrc[e], s1 = g_csrc[e + 1];
        const float4* p0 = (const float4*)(g_xlr + (size_t)s0 * 1024);
        const float4* p1 = (const float4*)(g_xlr + (size_t)s1 * 1024);
        float4 a0[4], a1[4];
        float lg0 = 0.f, lg1 = 0.f;
        #pragma unroll
        for (int j = 0; j < 4; j++) {
            a0[j] = p0[j * 32 + lane];
            a1[j] = p1[j * 32 + lane];
            float v;
            v = a0[j].x + xr4[j].x; v = v > 0.f ? v : 0.2f * v; lg0 += v * at4[j].x;
            v = a0[j].y + xr4[j].y; v = v > 0.f ? v : 0.2f * v; lg0 += v * at4[j].y;
            v = a0[j].z + xr4[j].z; v = v > 0.f ? v : 0.2f * v; lg0 += v * at4[j].z;
            v = a0[j].w + xr4[j].w; v = v > 0.f ? v : 0.2f * v; lg0 += v * at4[j].w;
            v = a1[j].x + xr4[j].x; v = v > 0.f ? v : 0.2f * v; lg1 += v * at4[j].x;
            v = a1[j].y + xr4[j].y; v = v > 0.f ? v : 0.2f * v; lg1 += v * at4[j].y;
            v = a1[j].z + xr4[j].z; v = v > 0.f ? v : 0.2f * v; lg1 += v * at4[j].z;
            v = a1[j].w + xr4[j].w; v = v > 0.f ? v : 0.2f * v; lg1 += v * at4[j].w;
        }
        #pragma unroll
        for (int o = 16; o; o >>= 1) {
            lg0 += __shfl_xor_sync(0xffffffffu, lg0, o);
            lg1 += __shfl_xor_sync(0xffffffffu, lg1, o);
        }

        float mx = fmaxf(lg0, lg1);
        if (mx > m) {
            float sc = expf(m - mx);   // first pair: exp(-inf)=0 zeroes state
            den *= sc;
            #pragma unroll
            for (int j = 0; j < 16; j++) accf[j] *= sc;
            m = mx;
        }
        float w0 = expf(lg0 - m), w1 = expf(lg1 - m);
        den += w0 + w1;
        #pragma unroll
        for (int j = 0; j < 4; j++) {
            accf[4 * j + 0] += w0 * a0[j].x + w1 * a1[j].x;
            accf[4 * j + 1] += w0 * a0[j].y + w1 * a1[j].y;
            accf[4 * j + 2] += w0 * a0[j].z + w1 * a1[j].z;
            accf[4 * j + 3] += w0 * a0[j].w + w1 * a1[j].w;
        }
    }
    for (; e < re; e++) {
        int s = g_csrc[e];
        const float4* pxl = (const float4*)(g_xlr + (size_t)s * 1024);
        float4 a[4];
        float lg = 0.f;
        #pragma unroll
        for (int j = 0; j < 4; j++) {
            a[j] = pxl[j * 32 + lane];
            float v;
            v = a[j].x + xr4[j].x; v = v > 0.f ? v : 0.2f * v; lg += v * at4[j].x;
            v = a[j].y + xr4[j].y; v = v > 0.f ? v : 0.2f * v; lg += v * at4[j].y;
            v = a[j].z + xr4[j].z; v = v > 0.f ? v : 0.2f * v; lg += v * at4[j].z;
            v = a[j].w + xr4[j].w; v = v > 0.f ? v : 0.2f * v; lg += v * at4[j].w;
        }
        #pragma unroll
        for (int o = 16; o; o >>= 1) lg += __shfl_xor_sync(0xffffffffu, lg, o);
        if (lg > m) {
            float sc = expf(m - lg);
            den *= sc;
            #pragma unroll
            for (int j = 0; j < 16; j++) accf[j] *= sc;
            m = lg;
        }
        float w = expf(lg - m);
        den += w;
        #pragma unroll
        for (int j = 0; j < 4; j++) {
            accf[4 * j + 0] += w * a[j].x;
            accf[4 * j + 1] += w * a[j].y;
            accf[4 * j + 2] += w * a[j].z;
            accf[4 * j + 3] += w * a[j].w;
        }
    }

    float inv = 1.0f / (den + 1e-16f);
    const float4* pb = (const float4*)bias;
    __nv_bfloat16* ph = g_ahi + (size_t)d * DE;
    __nv_bfloat16* pl = g_alo + (size_t)d * DE;
    #pragma unroll
    for (int j = 0; j < 4; j++) {
        float4 b = pb[j * 32 + lane];
        float t0 = tanhf(accf[4 * j + 0] * inv + b.x);
        float t1 = tanhf(accf[4 * j + 1] * inv + b.y);
        float t2 = tanhf(accf[4 * j + 2] * inv + b.z);
        float t3 = tanhf(accf[4 * j + 3] * inv + b.w);
        __nv_bfloat162 h01 = __floats2bfloat162_rn(t0, t1);
        __nv_bfloat162 h23 = __floats2bfloat162_rn(t2, t3);
        float l0 = t0 - __bfloat162float(__low2bfloat16(h01));
        float l1 = t1 - __bfloat162float(__high2bfloat16(h01));
        float l2 = t2 - __bfloat162float(__low2bfloat16(h23));
        float l3 = t3 - __bfloat162float(__high2bfloat16(h23));
        __nv_bfloat162 q01 = __floats2bfloat162_rn(l0, l1);
        __nv_bfloat162 q23 = __floats2bfloat162_rn(l2, l3);
        uint2 uh, ul;
        uh.x = *(uint32_t*)&h01; uh.y = *(uint32_t*)&h23;
        ul.x = *(uint32_t*)&q01; ul.y = *(uint32_t*)&q23;
        ((uint2*)ph)[j * 32 + lane] = uh;
        ((uint2*)pl)[j * 32 + lane] = ul;
    }
}

// ---------------- final MLP tail --------------------------------------------
__global__ void k_dot3(const float* __restrict__ A3, const float* __restrict__ c3) {
    int gt = blockIdx.x * blockDim.x + threadIdx.x;
    int n = gt >> 5;
    int lane = gt & 31;
    if (n >= NN) return;
    const float4* pm = (const float4*)(g_m2 + (size_t)n * DH);
    const float4* pw = (const float4*)A3;
    float acc = 0.f;
    #pragma unroll
    for (int i = 0; i < DH / 128; i++) {
        int k = i * 32 + lane;
        float4 m = pm[k], w = pw[k];
        acc += m.x * w.x + m.y * w.y + m.z * w.z + m.w * w.w;
    }
    #pragma unroll
    for (int o = 16; o; o >>= 1) acc += __shfl_xor_sync(0xffffffffu, acc, o);
    if (lane == 0) g_logit[n] = acc + c3[0];
}

__global__ void k_softmax(float* __restrict__ out) {
    __shared__ float sh[1024];
    int t = threadIdx.x;
    float m = -3.0e38f;
    for (int i = t; i < NN; i += 1024) m = fmaxf(m, g_logit[i]);
    sh[t] = m; __syncthreads();
    for (int s = 512; s; s >>= 1) { if (t < s) sh[t] = fmaxf(sh[t], sh[t + s]); __syncthreads(); }
    float gm = sh[0]; __syncthreads();
    float sum = 0.f;
    for (int i = t; i < NN; i += 1024) sum += expf(g_logit[i] - gm);
    sh[t] = sum; __syncthreads();
    for (int s = 512; s; s >>= 1) { if (t < s) sh[t] += sh[t + s]; __syncthreads(); }
    float gs = sh[0];
    for (int i = t; i < NN; i += 1024) out[i] = expf(g_logit[i] - gm) / gs;
}

// ---------------- host side -------------------------------------------------
static __nv_bfloat16 *s_ahi, *s_alo, *s_bhi, *s_blo, *s_whi, *s_wlo;

static void run_gemm(const __nv_bfloat16* Ahi, const __nv_bfloat16* Alo,
                     int K, int M, float* Cout, const float* bias, int mode,
                     __nv_bfloat16* Hi, __nv_bfloat16* Lo) {
    dim3 g(M / 128, (NN + 127) / 128);
    k_gemm_mma<<<g, 256, SMEM_GEMM>>>(Ahi, Alo, s_whi, s_wlo, Cout, NN, K, M,
                                      bias, mode, Hi, Lo);
}

static void prep_w(const float* W, int K, int M, int rofs) {
    dim3 g(K / 64, M / 32);
    k_prep_w<<<g, 256>>>(W, s_whi, s_wlo, K, M, rofs);
}

static void gat_layer(int din, const float* Wl, const float* Wr,
                      const float* att, const float* bias, float* xlr) {
    prep_w(Wl, din, DE, 0);
    prep_w(Wr, din, DE, DE);
    run_gemm(s_ahi, s_alo, din, 2 * DE, xlr, nullptr, 0, nullptr, nullptr);
    k_gat_edge<<<(NN * 32 + 255) / 256, 256>>>(att, bias);
}

extern "C" void kernel_launch(void* const* d_in, const int* in_sizes, int n_in,
                              void* d_out, int out_size) {
    const float* x   = (const float*)d_in[0];
    const int*   ei  = (const int*)d_in[1];
    const float* Wl1 = (const float*)d_in[2];
    const float* Wr1 = (const float*)d_in[3];
    const float* at1 = (const float*)d_in[4];
    const float* b1  = (const float*)d_in[5];
    const float* Wl2 = (const float*)d_in[6];
    const float* Wr2 = (const float*)d_in[7];
    const float* at2 = (const float*)d_in[8];
    const float* b2  = (const float*)d_in[9];
    const float* Wl3 = (const float*)d_in[10];
    const float* Wr3 = (const float*)d_in[11];
    const float* at3 = (const float*)d_in[12];
    const float* b3  = (const float*)d_in[13];
    const float* A1  = (const float*)d_in[14];
    const float* c1  = (const float*)d_in[15];
    const float* A2  = (const float*)d_in[16];
    const float* c2  = (const float*)d_in[17];
    const float* A3  = (const float*)d_in[18];
    const float* c3  = (const float*)d_in[19];
    float* out = (float*)d_out;

    cudaFuncSetAttribute(k_gemm_mma, cudaFuncAttributeMaxDynamicSharedMemorySize, SMEM_GEMM);

    float *xlr, *m1, *m2;
    cudaGetSymbolAddress((void**)&xlr, g_xlr);
    cudaGetSymbolAddress((void**)&m1,  g_m1);
    cudaGetSymbolAddress((void**)&m2,  g_m2);
    cudaGetSymbolAddress((void**)&s_ahi, g_ahi);
    cudaGetSymbolAddress((void**)&s_alo, g_alo);
    cudaGetSymbolAddress((void**)&s_bhi, g_bhi);
    cudaGetSymbolAddress((void**)&s_blo, g_blo);
    cudaGetSymbolAddress((void**)&s_whi, g_whi);
    cudaGetSymbolAddress((void**)&s_wlo, g_wlo);

    // edges + CSR by dst (4 launches)
    k_detect<<<1, 256>>>(ei);
    k_edges<<<(NE + 255) / 256, 256>>>(ei);
    k_scan<<<1, 1024>>>();
    k_scatter<<<(NE + 255) / 256, 256>>>();

    // layer 1 input split
    k_split<<<(NN * DI + 255) / 256, 256>>>(x, s_ahi, s_alo, NN * DI);

    gat_layer(DI, Wl1, Wr1, at1, b1, xlr);
    gat_layer(DE, Wl2, Wr2, at2, b2, xlr);
    gat_layer(DE, Wl3, Wr3, at3, b3, xlr);

    // MLP: split epilogue writes to g_bhi/g_blo (must not alias the A operand)
    prep_w(A1, DE, DH, 0);
    run_gemm(s_ahi, s_alo, DE, DH, m1, c1, 3, s_bhi, s_blo);
    prep_w(A2, DH, DH, 0);
    run_gemm(s_bhi, s_blo, DH, DH, m2, c2, 1, nullptr, nullptr);
    k_dot3<<<(NN * 32 + 255) / 256, 256>>>(A3, c3);
    k_softmax<<<1, 1024>>>(out);
}

// round 14
// speedup vs baseline: 1.0099x; 1.0099x over previous
#include <cuda_runtime.h>
#include <cuda_bf16.h>
#include <math.h>
#include <stdint.h>

#define NN 10000
#define NE 160000
#define DI 128
#define DE 512
#define DH 256

// ---------------- scratch (device globals; no allocation allowed) ----------
__device__ __align__(16) float g_xlr[NN * 2 * DE];   // [node][xl(512) | xr(512)]
__device__ int   g_src[NE];
__device__ int   g_dst[NE];
__device__ int   g_deg[NN];
__device__ int   g_rs[NN + 1];
__device__ int   g_cur[NN];
__device__ int   g_csrc[NE];
__device__ __align__(16) float g_m1[NN * DH];
__device__ __align__(16) float g_m2[NN * DH];
__device__ float g_logit[NN];
__device__ int   g_is64;
__device__ __align__(16) __nv_bfloat16 g_ahi[NN * DE];
__device__ __align__(16) __nv_bfloat16 g_alo[NN * DE];
__device__ __align__(16) __nv_bfloat16 g_bhi[NN * DH];   // MLP split output
__device__ __align__(16) __nv_bfloat16 g_blo[NN * DH];
__device__ __align__(16) __nv_bfloat16 g_whi[2 * DE * DE];
__device__ __align__(16) __nv_bfloat16 g_wlo[2 * DE * DE];

// ---------------- edge decode (+ degree histogram fused) --------------------
__global__ void k_detect(const int* __restrict__ w) {
    __shared__ int s;
    if (threadIdx.x == 0) s = 0;
    __syncthreads();
    int acc = 0;
    for (int i = threadIdx.x; i < 2048; i += 256) acc |= w[2 * i + 1];
    atomicOr(&s, acc);
    for (int i = threadIdx.x; i < NN; i += 256) g_deg[i] = 0;
    __syncthreads();
    if (threadIdx.x == 0) g_is64 = (s == 0) ? 1 : 0;
}

__global__ void k_edges(const int* __restrict__ w) {
    int i = blockIdx.x * blockDim.x + threadIdx.x;
    if (i >= NE) return;
    int s, d;
    if (g_is64) { s = w[2 * i]; d = w[2 * (NE + i)]; }
    else        { s = w[i];     d = w[NE + i]; }
    if ((unsigned)s >= NN) s = 0;
    if ((unsigned)d >= NN) d = 0;
    g_src[i] = s;
    g_dst[i] = d;
    atomicAdd(&g_deg[d], 1);
}

// coalesced chunked scan: 10 chunks of 1024, warp-shuffle within chunk
__global__ void k_scan() {
    __shared__ int wsum[32];
    __shared__ int sbase;
    int t = threadIdx.x;
    int lane = t & 31, w = t >> 5;
    if (t == 0) sbase = 0;
    __syncthreads();
    for (int c = 0; c < NN; c += 1024) {
        int idx = c + t;
        int v = (idx < NN) ? g_deg[idx] : 0;
        int inc = v;
        #pragma unroll
        for (int o = 1; o < 32; o <<= 1) {
            int u = __shfl_up_sync(0xffffffffu, inc, o);
            if (lane >= o) inc += u;
        }
        if (lane == 31) wsum[w] = inc;
        __syncthreads();
        if (w == 0) {
            int vv = wsum[lane];
            #pragma unroll
            for (int o = 1; o < 32; o <<= 1) {
                int u = __shfl_up_sync(0xffffffffu, vv, o);
                if (lane >= o) vv += u;
            }
            wsum[lane] = vv;
        }
        __syncthreads();
        int base = sbase + ((w > 0) ? wsum[w - 1] : 0) + inc - v;
        if (idx < NN) { g_rs[idx] = base; g_cur[idx] = base; }
        __syncthreads();
        if (t == 0) sbase += wsum[31];
        __syncthreads();
    }
    if (t == 0) g_rs[NN] = sbase;
}

__global__ void k_scatter() {
    int i = blockIdx.x * blockDim.x + threadIdx.x;
    if (i >= NE) return;
    int pos = atomicAdd(&g_cur[g_dst[i]], 1);
    g_csrc[pos] = g_src[i];
}

// ---------------- hi/lo split (layer-1 input only) ---------------------------
__global__ void k_split(const float* __restrict__ a, __nv_bfloat16* __restrict__ hi,
                        __nv_bfloat16* __restrict__ lo, int n) {
    int i = blockIdx.x * blockDim.x + threadIdx.x;
    if (i >= n) return;
    float v = a[i];
    __nv_bfloat16 h = __float2bfloat16_rn(v);
    hi[i] = h;
    lo[i] = __float2bfloat16_rn(v - __bfloat162float(h));
}

// ---------------- coalesced weight prep: W[K,M] -> WT[m+rofs][K] hi/lo -------
__global__ __launch_bounds__(256) void k_prep_w(
    const float* __restrict__ W, __nv_bfloat16* __restrict__ hiT,
    __nv_bfloat16* __restrict__ loT, int K, int M, int rofs) {
    __shared__ float s[64][33];
    int k0 = blockIdx.x * 64, m0 = blockIdx.y * 32;
    int tid = threadIdx.x;
    #pragma unroll
    for (int i = tid; i < 64 * 32; i += 256) {
        int kk = i >> 5, mm = i & 31;
        s[kk][mm] = W[(size_t)(k0 + kk) * M + m0 + mm];
    }
    __syncthreads();
    #pragma unroll
    for (int i = tid; i < 32 * 32; i += 256) {
        int mm = i >> 5, kp = i & 31;
        float v0 = s[2 * kp][mm], v1 = s[2 * kp + 1][mm];
        __nv_bfloat162 h2 = __floats2bfloat162_rn(v0, v1);
        float l0 = v0 - __bfloat162float(__low2bfloat16(h2));
        float l1 = v1 - __bfloat162float(__high2bfloat16(h2));
        __nv_bfloat162 l2 = __floats2bfloat162_rn(l0, l1);
        size_t ro = (size_t)(m0 + mm + rofs) * K + k0 + 2 * kp;
        *(uint32_t*)(hiT + ro) = *(uint32_t*)&h2;
        *(uint32_t*)(loT + ro) = *(uint32_t*)&l2;
    }
}

// ---------------- persistent cp.async + ldmatrix bf16 GEMM (3-pass hi/lo) ---
#define TPAD 40
#define TILE_E (128 * TPAD)
#define STAGE_E (4 * TILE_E)
#define SMEM_GEMM (2 * STAGE_E * 2)
#define GEMM_CTAS 296          // 2 per SM x 148 SMs

__device__ __forceinline__ void cpa16(uint32_t dst, const void* src, int sz) {
    asm volatile("cp.async.cg.shared.global [%0], [%1], 16, %2;"
                 :: "r"(dst), "l"(src), "r"(sz) : "memory");
}
__device__ __forceinline__ void cpa_commit() {
    asm volatile("cp.async.commit_group;" ::: "memory");
}
template<int N> __device__ __forceinline__ void cpa_wait() {
    asm volatile("cp.async.wait_group %0;" :: "n"(N) : "memory");
}
__device__ __forceinline__ void ldsm4(uint32_t* r, uint32_t addr) {
    asm volatile("ldmatrix.sync.aligned.m8n8.x4.shared.b16 {%0,%1,%2,%3}, [%4];"
                 : "=r"(r[0]), "=r"(r[1]), "=r"(r[2]), "=r"(r[3]) : "r"(addr));
}

// mode bit0: bias + leaky(0.1); mode bit1: also write bf16 hi/lo to Hi/Lo[r*M+c]
// NOTE: Hi/Lo must NOT alias Ahi/Alo (cross-CTA RAW race).
// Persistent: each CTA loops over output tiles (tile += gridDim.x).
__global__ __launch_bounds__(256, 2) void k_gemm_mma(
    const __nv_bfloat16* __restrict__ Ahi, const __nv_bfloat16* __restrict__ Alo,
    const __nv_bfloat16* __restrict__ BhiT, const __nv_bfloat16* __restrict__ BloT,
    float* __restrict__ C, int Nrows, int K, int M,
    const float* __restrict__ bias, int mode,
    __nv_bfloat16* __restrict__ Hi, __nv_bfloat16* __restrict__ Lo)
{
    extern __shared__ __nv_bfloat16 smem[];
    uint32_t sb = (uint32_t)__cvta_generic_to_shared(smem);

    int tid = threadIdx.x;
    int wid = tid >> 5, lane = tid & 31;
    int wm = wid & 1, wn = wid >> 1;
    int mBase = wm * 64, nBase = wn * 32;
    int g = lane >> 2, cw = lane & 3;
    int mat = lane >> 3, r8 = lane & 7;
    int rsel = (mat & 1) * 8 + r8;
    int csel = (mat >> 1) * 8;

    int nk = K / 32;               // even for all K used (4, 8, 16)
    int c0 = tid * 2;
    int ntx = M / 128;
    int ntiles = ntx * ((Nrows + 127) / 128);

    for (int tile = blockIdx.x; tile < ntiles; tile += gridDim.x) {
        int row0 = (tile / ntx) * 128;
        int col0 = (tile % ntx) * 128;

        float acc[4][4][4];
        #pragma unroll
        for (int a = 0; a < 4; a++)
            #pragma unroll
            for (int b = 0; b < 4; b++)
                #pragma unroll
                for (int c = 0; c < 4; c++) acc[a][b][c] = 0.f;

        auto prefetch = [&](int ck, int stage) {
            int kofs = ck * 32;
            uint32_t se = (uint32_t)stage * STAGE_E;
            #pragma unroll
            for (int i = 0; i < 2; i++) {
                int c = c0 + i;
                int r = c >> 2, seg = c & 3;
                uint32_t dA = sb + 2 * (se + r * TPAD + seg * 8);
                int gr = row0 + r;
                int szA = (gr < Nrows) ? 16 : 0;
                const __nv_bfloat16* pa = Ahi + (size_t)gr * K + kofs + seg * 8;
                const __nv_bfloat16* pl = Alo + (size_t)gr * K + kofs + seg * 8;
                if (szA == 0) { pa = Ahi; pl = Alo; }
                cpa16(dA, pa, szA);
                cpa16(dA + 2 * TILE_E, pl, szA);
                const __nv_bfloat16* pb = BhiT + (size_t)(col0 + r) * K + kofs + seg * 8;
                const __nv_bfloat16* pq = BloT + (size_t)(col0 + r) * K + kofs + seg * 8;
                cpa16(dA + 2 * (2 * TILE_E), pb, 16);
                cpa16(dA + 2 * (3 * TILE_E), pq, 16);
            }
            cpa_commit();
        };

        prefetch(0, 0);

        for (int ck = 0; ck < nk; ck++) {
            int stage = ck & 1;
            cpa_wait<0>();
            __syncthreads();      // publishes buf[ck]; all warps done reading buf[ck^1]
            if (ck + 1 < nk) prefetch(ck + 1, stage ^ 1);

            uint32_t se = (uint32_t)stage * STAGE_E;
            #pragma unroll
            for (int pass = 0; pass < 3; pass++) {
                uint32_t aoff = se + ((pass == 1) ? TILE_E : 0u);
                uint32_t boff = se + ((pass == 2) ? 3u * TILE_E : 2u * TILE_E);
                #pragma unroll
                for (int ks = 0; ks < 2; ks++) {
                    int kw = ks * 16 + csel;
                    uint32_t af[4][4];
                    #pragma unroll
                    for (int mi = 0; mi < 4; mi++)
                        ldsm4(af[mi], sb + 2 * (aoff + (uint32_t)(mBase + mi * 16 + rsel) * TPAD + kw));
                    uint32_t bfr[2][4];
                    #pragma unroll
                    for (int p = 0; p < 2; p++)
                        ldsm4(bfr[p], sb + 2 * (boff + (uint32_t)(nBase + p * 16 + rsel) * TPAD + kw));
                    #pragma unroll
                    for (int mi = 0; mi < 4; mi++)
                        #pragma unroll
                        for (int ni = 0; ni < 4; ni++) {
                            float* d = acc[mi][ni];
                            uint32_t b0 = bfr[ni >> 1][ni & 1];
                            uint32_t b1 = bfr[ni >> 1][2 + (ni & 1)];
                            asm volatile(
                                "mma.sync.aligned.m16n8k16.row.col.f32.bf16.bf16.f32 "
                                "{%0,%1,%2,%3}, {%4,%5,%6,%7}, {%8,%9}, {%0,%1,%2,%3};"
                                : "+f"(d[0]), "+f"(d[1]), "+f"(d[2]), "+f"(d[3])
                                : "r"(af[mi][0]), "r"(af[mi][1]), "r"(af[mi][2]), "r"(af[mi][3]),
                                  "r"(b0), "r"(b1));
                        }
                }
            }
        }

        #pragma unroll
        for (int mi = 0; mi < 4; mi++) {
            int r0 = row0 + mBase + mi * 16 + g;
            #pragma unroll
            for (int ni = 0; ni < 4; ni++) {
                int cc = col0 + nBase + ni * 8 + cw * 2;
                float v0 = acc[mi][ni][0], v1 = acc[mi][ni][1];
                float v2 = acc[mi][ni][2], v3 = acc[mi][ni][3];
                if (mode & 1) {
                    float b0 = bias[cc], b1 = bias[cc + 1];
                    v0 += b0; v0 = (v0 > 0.f) ? v0 : 0.1f * v0;
                    v1 += b1; v1 = (v1 > 0.f) ? v1 : 0.1f * v1;
                    v2 += b0; v2 = (v2 > 0.f) ? v2 : 0.1f * v2;
                    v3 += b1; v3 = (v3 > 0.f) ? v3 : 0.1f * v3;
                }
                if (r0 < Nrows) {
                    *(float2*)(C + (size_t)r0 * M + cc) = make_float2(v0, v1);
                    if (mode & 2) {
                        __nv_bfloat162 h2 = __floats2bfloat162_rn(v0, v1);
                        float l0 = v0 - __bfloat162float(__low2bfloat16(h2));
                        float l1 = v1 - __bfloat162float(__high2bfloat16(h2));
                        __nv_bfloat162 l2 = __floats2bfloat162_rn(l0, l1);
                        *(uint32_t*)(Hi + (size_t)r0 * M + cc) = *(uint32_t*)&h2;
                        *(uint32_t*)(Lo + (size_t)r0 * M + cc) = *(uint32_t*)&l2;
                    }
                }
                if (r0 + 8 < Nrows) {
                    *(float2*)(C + (size_t)(r0 + 8) * M + cc) = make_float2(v2, v3);
                    if (mode & 2) {
                        __nv_bfloat162 h2 = __floats2bfloat162_rn(v2, v3);
                        float l0 = v2 - __bfloat162float(__low2bfloat16(h2));
                        float l1 = v3 - __bfloat162float(__high2bfloat16(h2));
                        __nv_bfloat162 l2 = __floats2bfloat162_rn(l0, l1);
                        *(uint32_t*)(Hi + (size_t)(r0 + 8) * M + cc) = *(uint32_t*)&h2;
                        *(uint32_t*)(Lo + (size_t)(r0 + 8) * M + cc) = *(uint32_t*)&l2;
                    }
                }
            }
        }
        // no trailing sync needed: next tile's stage-0 prefetch cannot collide
        // with this tile's final (odd-stage) readers since nk is even.
    }
}

// ---------------- fused GATv2 edge kernel: one-pass online softmax ----------
__global__ __launch_bounds__(256) void k_gat_edge(const float* __restrict__ att,
                                                  const float* __restrict__ bias) {
    int gw = (blockIdx.x * 256 + threadIdx.x) >> 5;
    int lane = threadIdx.x & 31;
    if (gw >= NN) return;
    int d = gw;
    int rs = g_rs[d], re = g_rs[d + 1];

    float4 xr4[4], at4[4];
    const float4* pxr = (const float4*)(g_xlr + (size_t)d * 1024 + 512);
    const float4* pat = (const float4*)att;
    #pragma unroll
    for (int j = 0; j < 4; j++) {
        xr4[j] = pxr[j * 32 + lane];
        at4[j] = pat[j * 32 + lane];
    }

    float m = -3.0e38f;
    float den = 0.f;
    float accf[16];
    #pragma unroll
    for (int j = 0; j < 16; j++) accf[j] = 0.f;

    for (int e = rs; e < re; e++) {
        int s = g_csrc[e];
        const float4* pxl = (const float4*)(g_xlr + (size_t)s * 1024);
        float4 a[4];
        float lg = 0.f;
        #pragma unroll
        for (int j = 0; j < 4; j++) {
            a[j] = pxl[j * 32 + lane];
            float v;
            v = a[j].x + xr4[j].x; v = v > 0.f ? v : 0.2f * v; lg += v * at4[j].x;
            v = a[j].y + xr4[j].y; v = v > 0.f ? v : 0.2f * v; lg += v * at4[j].y;
            v = a[j].z + xr4[j].z; v = v > 0.f ? v : 0.2f * v; lg += v * at4[j].z;
            v = a[j].w + xr4[j].w; v = v > 0.f ? v : 0.2f * v; lg += v * at4[j].w;
        }
        #pragma unroll
        for (int o = 16; o; o >>= 1) lg += __shfl_xor_sync(0xffffffffu, lg, o);

        if (lg > m) {
            float sc = expf(m - lg);   // first edge: exp(-inf)=0 zeroes state
            den *= sc;
            #pragma unroll
            for (int j = 0; j < 16; j++) accf[j] *= sc;
            m = lg;
        }
        float w = expf(lg - m);
        den += w;
        #pragma unroll
        for (int j = 0; j < 4; j++) {
            accf[4 * j + 0] += w * a[j].x;
            accf[4 * j + 1] += w * a[j].y;
            accf[4 * j + 2] += w * a[j].z;
            accf[4 * j + 3] += w * a[j].w;
        }
    }

    float inv = 1.0f / (den + 1e-16f);
    const float4* pb = (const float4*)bias;
    __nv_bfloat16* ph = g_ahi + (size_t)d * DE;
    __nv_bfloat16* pl = g_alo + (size_t)d * DE;
    #pragma unroll
    for (int j = 0; j < 4; j++) {
        float4 b = pb[j * 32 + lane];
        float t0 = tanhf(accf[4 * j + 0] * inv + b.x);
        float t1 = tanhf(accf[4 * j + 1] * inv + b.y);
        float t2 = tanhf(accf[4 * j + 2] * inv + b.z);
        float t3 = tanhf(accf[4 * j + 3] * inv + b.w);
        __nv_bfloat162 h01 = __floats2bfloat162_rn(t0, t1);
        __nv_bfloat162 h23 = __floats2bfloat162_rn(t2, t3);
        float l0 = t0 - __bfloat162float(__low2bfloat16(h01));
        float l1 = t1 - __bfloat162float(__high2bfloat16(h01));
        float l2 = t2 - __bfloat162float(__low2bfloat16(h23));
        float l3 = t3 - __bfloat162float(__high2bfloat16(h23));
        __nv_bfloat162 q01 = __floats2bfloat162_rn(l0, l1);
        __nv_bfloat162 q23 = __floats2bfloat162_rn(l2, l3);
        uint2 uh, ul;
        uh.x = *(uint32_t*)&h01; uh.y = *(uint32_t*)&h23;
        ul.x = *(uint32_t*)&q01; ul.y = *(uint32_t*)&q23;
        ((uint2*)ph)[j * 32 + lane] = uh;
        ((uint2*)pl)[j * 32 + lane] = ul;
    }
}

// ---------------- final MLP tail --------------------------------------------
__global__ void k_dot3(const float* __restrict__ A3, const float* __restrict__ c3) {
    int gt = blockIdx.x * blockDim.x + threadIdx.x;
    int n = gt >> 5;
    int lane = gt & 31;
    if (n >= NN) return;
    const float4* pm = (const float4*)(g_m2 + (size_t)n * DH);
    const float4* pw = (const float4*)A3;
    float acc = 0.f;
    #pragma unroll
    for (int i = 0; i < DH / 128; i++) {
        int k = i * 32 + lane;
        float4 m = pm[k], w = pw[k];
        acc += m.x * w.x + m.y * w.y + m.z * w.z + m.w * w.w;
    }
    #pragma unroll
    for (int o = 16; o; o >>= 1) acc += __shfl_xor_sync(0xffffffffu, acc, o);
    if (lane == 0) g_logit[n] = acc + c3[0];
}

__global__ void k_softmax(float* __restrict__ out) {
    __shared__ float sh[1024];
    int t = threadIdx.x;
    float m = -3.0e38f;
    for (int i = t; i < NN; i += 1024) m = fmaxf(m, g_logit[i]);
    sh[t] = m; __syncthreads();
    for (int s = 512; s; s >>= 1) { if (t < s) sh[t] = fmaxf(sh[t], sh[t + s]); __syncthreads(); }
    float gm = sh[0]; __syncthreads();
    float sum = 0.f;
    for (int i = t; i < NN; i += 1024) sum += expf(g_logit[i] - gm);
    sh[t] = sum; __syncthreads();
    for (int s = 512; s; s >>= 1) { if (t < s) sh[t] += sh[t + s]; __syncthreads(); }
    float gs = sh[0];
    for (int i = t; i < NN; i += 1024) out[i] = expf(g_logit[i] - gm) / gs;
}

// ---------------- host side -------------------------------------------------
static __nv_bfloat16 *s_ahi, *s_alo, *s_bhi, *s_blo, *s_whi, *s_wlo;

static void run_gemm(const __nv_bfloat16* Ahi, const __nv_bfloat16* Alo,
                     int K, int M, float* Cout, const float* bias, int mode,
                     __nv_bfloat16* Hi, __nv_bfloat16* Lo) {
    int ntiles = (M / 128) * ((NN + 127) / 128);
    int grid = (ntiles < GEMM_CTAS) ? ntiles : GEMM_CTAS;
    k_gemm_mma<<<grid, 256, SMEM_GEMM>>>(Ahi, Alo, s_whi, s_wlo, Cout, NN, K, M,
                                         bias, mode, Hi, Lo);
}

static void prep_w(const float* W, int K, int M, int rofs) {
    dim3 g(K / 64, M / 32);
    k_prep_w<<<g, 256>>>(W, s_whi, s_wlo, K, M, rofs);
}

static void gat_layer(int din, const float* Wl, const float* Wr,
                      const float* att, const float* bias, float* xlr) {
    prep_w(Wl, din, DE, 0);
    prep_w(Wr, din, DE, DE);
    run_gemm(s_ahi, s_alo, din, 2 * DE, xlr, nullptr, 0, nullptr, nullptr);
    k_gat_edge<<<(NN * 32 + 255) / 256, 256>>>(att, bias);
}

extern "C" void kernel_launch(void* const* d_in, const int* in_sizes, int n_in,
                              void* d_out, int out_size) {
    const float* x   = (const float*)d_in[0];
    const int*   ei  = (const int*)d_in[1];
    const float* Wl1 = (const float*)d_in[2];
    const float* Wr1 = (const float*)d_in[3];
    const float* at1 = (const float*)d_in[4];
    const float* b1  = (const float*)d_in[5];
    const float* Wl2 = (const float*)d_in[6];
    const float* Wr2 = (const float*)d_in[7];
    const float* at2 = (const float*)d_in[8];
    const float* b2  = (const float*)d_in[9];
    const float* Wl3 = (const float*)d_in[10];
    const float* Wr3 = (const float*)d_in[11];
    const float* at3 = (const float*)d_in[12];
    const float* b3  = (const float*)d_in[13];
    const float* A1  = (const float*)d_in[14];
    const float* c1  = (const float*)d_in[15];
    const float* A2  = (const float*)d_in[16];
    const float* c2  = (const float*)d_in[17];
    const float* A3  = (const float*)d_in[18];
    const float* c3  = (const float*)d_in[19];
    float* out = (float*)d_out;

    cudaFuncSetAttribute(k_gemm_mma, cudaFuncAttributeMaxDynamicSharedMemorySize, SMEM_GEMM);

    float *xlr, *m1, *m2;
    cudaGetSymbolAddress((void**)&xlr, g_xlr);
    cudaGetSymbolAddress((void**)&m1,  g_m1);
    cudaGetSymbolAddress((void**)&m2,  g_m2);
    cudaGetSymbolAddress((void**)&s_ahi, g_ahi);
    cudaGetSymbolAddress((void**)&s_alo, g_alo);
    cudaGetSymbolAddress((void**)&s_bhi, g_bhi);
    cudaGetSymbolAddress((void**)&s_blo, g_blo);
    cudaGetSymbolAddress((void**)&s_whi, g_whi);
    cudaGetSymbolAddress((void**)&s_wlo, g_wlo);

    // edges + CSR by dst (4 launches)
    k_detect<<<1, 256>>>(ei);
    k_edges<<<(NE + 255) / 256, 256>>>(ei);
    k_scan<<<1, 1024>>>();
    k_scatter<<<(NE + 255) / 256, 256>>>();

    // layer 1 input split
    k_split<<<(NN * DI + 255) / 256, 256>>>(x, s_ahi, s_alo, NN * DI);

    gat_layer(DI, Wl1, Wr1, at1, b1, xlr);
    gat_layer(DE, Wl2, Wr2, at2, b2, xlr);
    gat_layer(DE, Wl3, Wr3, at3, b3, xlr);

    // MLP: split epilogue writes to g_bhi/g_blo (must not alias the A operand)
    prep_w(A1, DE, DH, 0);
    run_gemm(s_ahi, s_alo, DE, DH, m1, c1, 3, s_bhi, s_blo);
    prep_w(A2, DH, DH, 0);
    run_gemm(s_bhi, s_blo, DH, DH, m2, c2, 1, nullptr, nullptr);
    k_dot3<<<(NN * 32 + 255) / 256, 256>>>(A3, c3);
    k_softmax<<<1, 1024>>>(out);
}

// round 15
// speedup vs baseline: 1.0511x; 1.0408x over previous
#include <cuda_runtime.h>
#include <cuda_bf16.h>
#include <math.h>
#include <stdint.h>

#define NN 10000
#define NE 160000
#define DI 128
#define DE 512
#define DH 256

// ---------------- scratch (device globals; no allocation allowed) ----------
__device__ __align__(16) float g_xlr[NN * 2 * DE];   // [node][xl(512) | xr(512)]
__device__ int   g_src[NE];
__device__ int   g_dst[NE];
__device__ int   g_deg[NN];
__device__ int   g_rs[NN + 1];
__device__ int   g_cur[NN];
__device__ int   g_csrc[NE];
__device__ __align__(16) float g_m1[NN * DH];
__device__ float g_logit[NN];
__device__ int   g_is64;
__device__ __align__(16) __nv_bfloat16 g_ahi[NN * DE];
__device__ __align__(16) __nv_bfloat16 g_alo[NN * DE];
__device__ __align__(16) __nv_bfloat16 g_bhi[NN * DH];   // MLP split output
__device__ __align__(16) __nv_bfloat16 g_blo[NN * DH];
__device__ __align__(16) __nv_bfloat16 g_whi[2 * DE * DE];
__device__ __align__(16) __nv_bfloat16 g_wlo[2 * DE * DE];

// ---------------- detect dtype + zero deg/logit -----------------------------
__global__ void k_detect(const int* __restrict__ w) {
    __shared__ int s;
    if (threadIdx.x == 0) s = 0;
    __syncthreads();
    int acc = 0;
    for (int i = threadIdx.x; i < 2048; i += 256) acc |= w[2 * i + 1];
    atomicOr(&s, acc);
    for (int i = threadIdx.x; i < NN; i += 256) { g_deg[i] = 0; g_logit[i] = 0.f; }
    __syncthreads();
    if (threadIdx.x == 0) g_is64 = (s == 0) ? 1 : 0;
}

// ---------------- edge decode + histogram + layer-1 split (fused) -----------
__global__ void k_edges_split(const int* __restrict__ w, const float* __restrict__ x,
                              __nv_bfloat16* __restrict__ hi, __nv_bfloat16* __restrict__ lo,
                              int nsplit) {
    int i = blockIdx.x * blockDim.x + threadIdx.x;
    if (i < NE) {
        int s, d;
        if (g_is64) { s = w[2 * i]; d = w[2 * (NE + i)]; }
        else        { s = w[i];     d = w[NE + i]; }
        if ((unsigned)s >= NN) s = 0;
        if ((unsigned)d >= NN) d = 0;
        g_src[i] = s;
        g_dst[i] = d;
        atomicAdd(&g_deg[d], 1);
    } else {
        int j = i - NE;
        if (j < nsplit) {
            float v = x[j];
            __nv_bfloat16 h = __float2bfloat16_rn(v);
            hi[j] = h;
            lo[j] = __float2bfloat16_rn(v - __bfloat162float(h));
        }
    }
}

// coalesced chunked scan: 10 chunks of 1024, warp-shuffle within chunk
__global__ void k_scan() {
    __shared__ int wsum[32];
    __shared__ int sbase;
    int t = threadIdx.x;
    int lane = t & 31, w = t >> 5;
    if (t == 0) sbase = 0;
    __syncthreads();
    for (int c = 0; c < NN; c += 1024) {
        int idx = c + t;
        int v = (idx < NN) ? g_deg[idx] : 0;
        int inc = v;
        #pragma unroll
        for (int o = 1; o < 32; o <<= 1) {
            int u = __shfl_up_sync(0xffffffffu, inc, o);
            if (lane >= o) inc += u;
        }
        if (lane == 31) wsum[w] = inc;
        __syncthreads();
        if (w == 0) {
            int vv = wsum[lane];
            #pragma unroll
            for (int o = 1; o < 32; o <<= 1) {
                int u = __shfl_up_sync(0xffffffffu, vv, o);
                if (lane >= o) vv += u;
            }
            wsum[lane] = vv;
        }
        __syncthreads();
        int base = sbase + ((w > 0) ? wsum[w - 1] : 0) + inc - v;
        if (idx < NN) { g_rs[idx] = base; g_cur[idx] = base; }
        __syncthreads();
        if (t == 0) sbase += wsum[31];
        __syncthreads();
    }
    if (t == 0) g_rs[NN] = sbase;
}

__global__ void k_scatter() {
    int i = blockIdx.x * blockDim.x + threadIdx.x;
    if (i >= NE) return;
    int pos = atomicAdd(&g_cur[g_dst[i]], 1);
    g_csrc[pos] = g_src[i];
}

// ---------------- coalesced weight prep (dual via blockIdx.z) ---------------
// W[K,M] -> WT[m + z*M][K] hi/lo
__global__ __launch_bounds__(256) void k_prep_w2(
    const float* __restrict__ W0, const float* __restrict__ W1,
    __nv_bfloat16* __restrict__ hiT, __nv_bfloat16* __restrict__ loT, int K, int M) {
    __shared__ float s[64][33];
    const float* W = blockIdx.z ? W1 : W0;
    int rofs = blockIdx.z * M;
    int k0 = blockIdx.x * 64, m0 = blockIdx.y * 32;
    int tid = threadIdx.x;
    #pragma unroll
    for (int i = tid; i < 64 * 32; i += 256) {
        int kk = i >> 5, mm = i & 31;
        s[kk][mm] = W[(size_t)(k0 + kk) * M + m0 + mm];
    }
    __syncthreads();
    #pragma unroll
    for (int i = tid; i < 32 * 32; i += 256) {
        int mm = i >> 5, kp = i & 31;
        float v0 = s[2 * kp][mm], v1 = s[2 * kp + 1][mm];
        __nv_bfloat162 h2 = __floats2bfloat162_rn(v0, v1);
        float l0 = v0 - __bfloat162float(__low2bfloat16(h2));
        float l1 = v1 - __bfloat162float(__high2bfloat16(h2));
        __nv_bfloat162 l2 = __floats2bfloat162_rn(l0, l1);
        size_t ro = (size_t)(m0 + mm + rofs) * K + k0 + 2 * kp;
        *(uint32_t*)(hiT + ro) = *(uint32_t*)&h2;
        *(uint32_t*)(loT + ro) = *(uint32_t*)&l2;
    }
}

// ---------------- persistent cp.async + ldmatrix bf16 GEMM (3-pass hi/lo) ---
#define TPAD 40
#define TILE_E (128 * TPAD)
#define STAGE_E (4 * TILE_E)
#define SMEM_GEMM (2 * STAGE_E * 2)
#define GEMM_CTAS 296

__device__ __forceinline__ void cpa16(uint32_t dst, const void* src, int sz) {
    asm volatile("cp.async.cg.shared.global [%0], [%1], 16, %2;"
                 :: "r"(dst), "l"(src), "r"(sz) : "memory");
}
__device__ __forceinline__ void cpa_commit() {
    asm volatile("cp.async.commit_group;" ::: "memory");
}
template<int N> __device__ __forceinline__ void cpa_wait() {
    asm volatile("cp.async.wait_group %0;" :: "n"(N) : "memory");
}
__device__ __forceinline__ void ldsm4(uint32_t* r, uint32_t addr) {
    asm volatile("ldmatrix.sync.aligned.m8n8.x4.shared.b16 {%0,%1,%2,%3}, [%4];"
                 : "=r"(r[0]), "=r"(r[1]), "=r"(r[2]), "=r"(r[3]) : "r"(addr));
}

// mode bits: 1 = bias + leaky(0.1); 2 = write bf16 hi/lo to Hi/Lo;
//            4 = partial dot with A3v -> atomicAdd g_logit[row]; 8 = skip C write
__global__ __launch_bounds__(256, 2) void k_gemm_mma(
    const __nv_bfloat16* __restrict__ Ahi, const __nv_bfloat16* __restrict__ Alo,
    const __nv_bfloat16* __restrict__ BhiT, const __nv_bfloat16* __restrict__ BloT,
    float* __restrict__ C, int Nrows, int K, int M,
    const float* __restrict__ bias, int mode,
    __nv_bfloat16* __restrict__ Hi, __nv_bfloat16* __restrict__ Lo,
    const float* __restrict__ A3v)
{
    extern __shared__ __nv_bfloat16 smem[];
    uint32_t sb = (uint32_t)__cvta_generic_to_shared(smem);

    int tid = threadIdx.x;
    int wid = tid >> 5, lane = tid & 31;
    int wm = wid & 1, wn = wid >> 1;
    int mBase = wm * 64, nBase = wn * 32;
    int g = lane >> 2, cw = lane & 3;
    int mat = lane >> 3, r8 = lane & 7;
    int rsel = (mat & 1) * 8 + r8;
    int csel = (mat >> 1) * 8;

    int nk = K / 32;               // even for all K used
    int c0 = tid * 2;
    int ntx = M / 128;
    int ntiles = ntx * ((Nrows + 127) / 128);

    for (int tile = blockIdx.x; tile < ntiles; tile += gridDim.x) {
        int row0 = (tile / ntx) * 128;
        int col0 = (tile % ntx) * 128;

        float acc[4][4][4];
        #pragma unroll
        for (int a = 0; a < 4; a++)
            #pragma unroll
            for (int b = 0; b < 4; b++)
                #pragma unroll
                for (int c = 0; c < 4; c++) acc[a][b][c] = 0.f;

        auto prefetch = [&](int ck, int stage) {
            int kofs = ck * 32;
            uint32_t se = (uint32_t)stage * STAGE_E;
            #pragma unroll
            for (int i = 0; i < 2; i++) {
                int c = c0 + i;
                int r = c >> 2, seg = c & 3;
                uint32_t dA = sb + 2 * (se + r * TPAD + seg * 8);
                int gr = row0 + r;
                int szA = (gr < Nrows) ? 16 : 0;
                const __nv_bfloat16* pa = Ahi + (size_t)gr * K + kofs + seg * 8;
                const __nv_bfloat16* pl = Alo + (size_t)gr * K + kofs + seg * 8;
                if (szA == 0) { pa = Ahi; pl = Alo; }
                cpa16(dA, pa, szA);
                cpa16(dA + 2 * TILE_E, pl, szA);
                const __nv_bfloat16* pb = BhiT + (size_t)(col0 + r) * K + kofs + seg * 8;
                const __nv_bfloat16* pq = BloT + (size_t)(col0 + r) * K + kofs + seg * 8;
                cpa16(dA + 2 * (2 * TILE_E), pb, 16);
                cpa16(dA + 2 * (3 * TILE_E), pq, 16);
            }
            cpa_commit();
        };

        prefetch(0, 0);

        for (int ck = 0; ck < nk; ck++) {
            int stage = ck & 1;
            cpa_wait<0>();
            __syncthreads();
            if (ck + 1 < nk) prefetch(ck + 1, stage ^ 1);

            uint32_t se = (uint32_t)stage * STAGE_E;
            #pragma unroll
            for (int pass = 0; pass < 3; pass++) {
                uint32_t aoff = se + ((pass == 1) ? TILE_E : 0u);
                uint32_t boff = se + ((pass == 2) ? 3u * TILE_E : 2u * TILE_E);
                #pragma unroll
                for (int ks = 0; ks < 2; ks++) {
                    int kw = ks * 16 + csel;
                    uint32_t af[4][4];
                    #pragma unroll
                    for (int mi = 0; mi < 4; mi++)
                        ldsm4(af[mi], sb + 2 * (aoff + (uint32_t)(mBase + mi * 16 + rsel) * TPAD + kw));
                    uint32_t bfr[2][4];
                    #pragma unroll
                    for (int p = 0; p < 2; p++)
                        ldsm4(bfr[p], sb + 2 * (boff + (uint32_t)(nBase + p * 16 + rsel) * TPAD + kw));
                    #pragma unroll
                    for (int mi = 0; mi < 4; mi++)
                        #pragma unroll
                        for (int ni = 0; ni < 4; ni++) {
                            float* d = acc[mi][ni];
                            uint32_t b0 = bfr[ni >> 1][ni & 1];
                            uint32_t b1 = bfr[ni >> 1][2 + (ni & 1)];
                            asm volatile(
                                "mma.sync.aligned.m16n8k16.row.col.f32.bf16.bf16.f32 "
                                "{%0,%1,%2,%3}, {%4,%5,%6,%7}, {%8,%9}, {%0,%1,%2,%3};"
                                : "+f"(d[0]), "+f"(d[1]), "+f"(d[2]), "+f"(d[3])
                                : "r"(af[mi][0]), "r"(af[mi][1]), "r"(af[mi][2]), "r"(af[mi][3]),
                                  "r"(b0), "r"(b1));
                        }
                }
            }
        }

        #pragma unroll
        for (int mi = 0; mi < 4; mi++) {
            int r0 = row0 + mBase + mi * 16 + g;
            float dot0 = 0.f, dot1 = 0.f;
            #pragma unroll
            for (int ni = 0; ni < 4; ni++) {
                int cc = col0 + nBase + ni * 8 + cw * 2;
                float v0 = acc[mi][ni][0], v1 = acc[mi][ni][1];
                float v2 = acc[mi][ni][2], v3 = acc[mi][ni][3];
                if (mode & 1) {
                    float b0 = bias[cc], b1 = bias[cc + 1];
                    v0 += b0; v0 = (v0 > 0.f) ? v0 : 0.1f * v0;
                    v1 += b1; v1 = (v1 > 0.f) ? v1 : 0.1f * v1;
                    v2 += b0; v2 = (v2 > 0.f) ? v2 : 0.1f * v2;
                    v3 += b1; v3 = (v3 > 0.f) ? v3 : 0.1f * v3;
                }
                if (mode & 4) {
                    float w0 = A3v[cc], w1 = A3v[cc + 1];
                    dot0 += v0 * w0 + v1 * w1;
                    dot1 += v2 * w0 + v3 * w1;
                }
                if (r0 < Nrows) {
                    if (!(mode & 8))
                        *(float2*)(C + (size_t)r0 * M + cc) = make_float2(v0, v1);
                    if (mode & 2) {
                        __nv_bfloat162 h2 = __floats2bfloat162_rn(v0, v1);
                        float l0 = v0 - __bfloat162float(__low2bfloat16(h2));
                        float l1 = v1 - __bfloat162float(__high2bfloat16(h2));
                        __nv_bfloat162 l2 = __floats2bfloat162_rn(l0, l1);
                        *(uint32_t*)(Hi + (size_t)r0 * M + cc) = *(uint32_t*)&h2;
                        *(uint32_t*)(Lo + (size_t)r0 * M + cc) = *(uint32_t*)&l2;
                    }
                }
                if (r0 + 8 < Nrows) {
                    if (!(mode & 8))
                        *(float2*)(C + (size_t)(r0 + 8) * M + cc) = make_float2(v2, v3);
                    if (mode & 2) {
                        __nv_bfloat162 h2 = __floats2bfloat162_rn(v2, v3);
                        float l0 = v2 - __bfloat162float(__low2bfloat16(h2));
                        float l1 = v3 - __bfloat162float(__high2bfloat16(h2));
                        __nv_bfloat162 l2 = __floats2bfloat162_rn(l0, l1);
                        *(uint32_t*)(Hi + (size_t)(r0 + 8) * M + cc) = *(uint32_t*)&h2;
                        *(uint32_t*)(Lo + (size_t)(r0 + 8) * M + cc) = *(uint32_t*)&l2;
                    }
                }
            }
            if (mode & 4) {
                // reduce over the 4 lanes (cw) sharing this row, then atomicAdd
                #pragma unroll
                for (int o = 1; o < 4; o <<= 1) {
                    dot0 += __shfl_xor_sync(0xffffffffu, dot0, o);
                    dot1 += __shfl_xor_sync(0xffffffffu, dot1, o);
                }
                if (cw == 0) {
                    if (r0 < Nrows)     atomicAdd(&g_logit[r0], dot0);
                    if (r0 + 8 < Nrows) atomicAdd(&g_logit[r0 + 8], dot1);
                }
            }
        }
    }
}

// ---------------- fused GATv2 edge kernel: one-pass online softmax ----------
__global__ __launch_bounds__(256) void k_gat_edge(const float* __restrict__ att,
                                                  const float* __restrict__ bias) {
    int gw = (blockIdx.x * 256 + threadIdx.x) >> 5;
    int lane = threadIdx.x & 31;
    if (gw >= NN) return;
    int d = gw;
    int rs = g_rs[d], re = g_rs[d + 1];

    float4 xr4[4], at4[4];
    const float4* pxr = (const float4*)(g_xlr + (size_t)d * 1024 + 512);
    const float4* pat = (const float4*)att;
    #pragma unroll
    for (int j = 0; j < 4; j++) {
        xr4[j] = pxr[j * 32 + lane];
        at4[j] = pat[j * 32 + lane];
    }

    float m = -3.0e38f;
    float den = 0.f;
    float accf[16];
    #pragma unroll
    for (int j = 0; j < 16; j++) accf[j] = 0.f;

    for (int e = rs; e < re; e++) {
        int s = g_csrc[e];
        const float4* pxl = (const float4*)(g_xlr + (size_t)s * 1024);
        float4 a[4];
        float lg = 0.f;
        #pragma unroll
        for (int j = 0; j < 4; j++) {
            a[j] = pxl[j * 32 + lane];
            float v;
            v = a[j].x + xr4[j].x; v = v > 0.f ? v : 0.2f * v; lg += v * at4[j].x;
            v = a[j].y + xr4[j].y; v = v > 0.f ? v : 0.2f * v; lg += v * at4[j].y;
            v = a[j].z + xr4[j].z; v = v > 0.f ? v : 0.2f * v; lg += v * at4[j].z;
            v = a[j].w + xr4[j].w; v = v > 0.f ? v : 0.2f * v; lg += v * at4[j].w;
        }
        #pragma unroll
        for (int o = 16; o; o >>= 1) lg += __shfl_xor_sync(0xffffffffu, lg, o);

        if (lg > m) {
            float sc = expf(m - lg);   // first edge: exp(-inf)=0 zeroes state
            den *= sc;
            #pragma unroll
            for (int j = 0; j < 16; j++) accf[j] *= sc;
            m = lg;
        }
        float w = expf(lg - m);
        den += w;
        #pragma unroll
        for (int j = 0; j < 4; j++) {
            accf[4 * j + 0] += w * a[j].x;
            accf[4 * j + 1] += w * a[j].y;
            accf[4 * j + 2] += w * a[j].z;
            accf[4 * j + 3] += w * a[j].w;
        }
    }

    float inv = 1.0f / (den + 1e-16f);
    const float4* pb = (const float4*)bias;
    __nv_bfloat16* ph = g_ahi + (size_t)d * DE;
    __nv_bfloat16* pl = g_alo + (size_t)d * DE;
    #pragma unroll
    for (int j = 0; j < 4; j++) {
        float4 b = pb[j * 32 + lane];
        float t0 = tanhf(accf[4 * j + 0] * inv + b.x);
        float t1 = tanhf(accf[4 * j + 1] * inv + b.y);
        float t2 = tanhf(accf[4 * j + 2] * inv + b.z);
        float t3 = tanhf(accf[4 * j + 3] * inv + b.w);
        __nv_bfloat162 h01 = __floats2bfloat162_rn(t0, t1);
        __nv_bfloat162 h23 = __floats2bfloat162_rn(t2, t3);
        float l0 = t0 - __bfloat162float(__low2bfloat16(h01));
        float l1 = t1 - __bfloat162float(__high2bfloat16(h01));
        float l2 = t2 - __bfloat162float(__low2bfloat16(h23));
        float l3 = t3 - __bfloat162float(__high2bfloat16(h23));
        __nv_bfloat162 q01 = __floats2bfloat162_rn(l0, l1);
        __nv_bfloat162 q23 = __floats2bfloat162_rn(l2, l3);
        uint2 uh, ul;
        uh.x = *(uint32_t*)&h01; uh.y = *(uint32_t*)&h23;
        ul.x = *(uint32_t*)&q01; ul.y = *(uint32_t*)&q23;
        ((uint2*)ph)[j * 32 + lane] = uh;
        ((uint2*)pl)[j * 32 + lane] = ul;
    }
}

// ---------------- softmax over nodes (register-cached, 1 global pass) -------
__global__ void k_softmax(float* __restrict__ out) {
    __shared__ float sh[1024];
    int t = threadIdx.x;
    float v[10];
    float m = -3.0e38f;
    #pragma unroll
    for (int j = 0; j < 10; j++) {
        int idx = t + j * 1024;
        v[j] = (idx < NN) ? g_logit[idx] : -3.0e38f;
        m = fmaxf(m, v[j]);
    }
    sh[t] = m; __syncthreads();
    for (int s = 512; s; s >>= 1) { if (t < s) sh[t] = fmaxf(sh[t], sh[t + s]); __syncthreads(); }
    float gm = sh[0]; __syncthreads();
    float sum = 0.f;
    #pragma unroll
    for (int j = 0; j < 10; j++) {
        int idx = t + j * 1024;
        if (idx < NN) { v[j] = expf(v[j] - gm); sum += v[j]; }
    }
    sh[t] = sum; __syncthreads();
    for (int s = 512; s; s >>= 1) { if (t < s) sh[t] += sh[t + s]; __syncthreads(); }
    float gs = sh[0];
    float inv = 1.0f / gs;
    #pragma unroll
    for (int j = 0; j < 10; j++) {
        int idx = t + j * 1024;
        if (idx < NN) out[idx] = v[j] * inv;
    }
}

// ---------------- host side -------------------------------------------------
static __nv_bfloat16 *s_ahi, *s_alo, *s_bhi, *s_blo, *s_whi, *s_wlo;

static void run_gemm(const __nv_bfloat16* Ahi, const __nv_bfloat16* Alo,
                     int K, int M, float* Cout, const float* bias, int mode,
                     __nv_bfloat16* Hi, __nv_bfloat16* Lo, const float* A3v) {
    int ntiles = (M / 128) * ((NN + 127) / 128);
    int grid = (ntiles < GEMM_CTAS) ? ntiles : GEMM_CTAS;
    k_gemm_mma<<<grid, 256, SMEM_GEMM>>>(Ahi, Alo, s_whi, s_wlo, Cout, NN, K, M,
                                         bias, mode, Hi, Lo, A3v);
}

static void prep_w(const float* W0, const float* W1, int K, int M, int nz) {
    dim3 g(K / 64, M / 32, nz);
    k_prep_w2<<<g, 256>>>(W0, W1, s_whi, s_wlo, K, M);
}

static void gat_layer(int din, const float* Wl, const float* Wr,
                      const float* att, const float* bias, float* xlr) {
    prep_w(Wl, Wr, din, DE, 2);
    run_gemm(s_ahi, s_alo, din, 2 * DE, xlr, nullptr, 0, nullptr, nullptr, nullptr);
    k_gat_edge<<<(NN * 32 + 255) / 256, 256>>>(att, bias);
}

extern "C" void kernel_launch(void* const* d_in, const int* in_sizes, int n_in,
                              void* d_out, int out_size) {
    const float* x   = (const float*)d_in[0];
    const int*   ei  = (const int*)d_in[1];
    const float* Wl1 = (const float*)d_in[2];
    const float* Wr1 = (const float*)d_in[3];
    const float* at1 = (const float*)d_in[4];
    const float* b1  = (const float*)d_in[5];
    const float* Wl2 = (const float*)d_in[6];
    const float* Wr2 = (const float*)d_in[7];
    const float* at2 = (const float*)d_in[8];
    const float* b2  = (const float*)d_in[9];
    const float* Wl3 = (const float*)d_in[10];
    const float* Wr3 = (const float*)d_in[11];
    const float* at3 = (const float*)d_in[12];
    const float* b3  = (const float*)d_in[13];
    const float* A1  = (const float*)d_in[14];
    const float* c1  = (const float*)d_in[15];
    const float* A2  = (const float*)d_in[16];
    const float* c2  = (const float*)d_in[17];
    const float* A3  = (const float*)d_in[18];
    // c3 cancels exactly in the node softmax (constant shift) — unused.
    float* out = (float*)d_out;

    cudaFuncSetAttribute(k_gemm_mma, cudaFuncAttributeMaxDynamicSharedMemorySize, SMEM_GEMM);

    float *xlr, *m1;
    cudaGetSymbolAddress((void**)&xlr, g_xlr);
    cudaGetSymbolAddress((void**)&m1,  g_m1);
    cudaGetSymbolAddress((void**)&s_ahi, g_ahi);
    cudaGetSymbolAddress((void**)&s_alo, g_alo);
    cudaGetSymbolAddress((void**)&s_bhi, g_bhi);
    cudaGetSymbolAddress((void**)&s_blo, g_blo);
    cudaGetSymbolAddress((void**)&s_whi, g_whi);
    cudaGetSymbolAddress((void**)&s_wlo, g_wlo);

    // CSR + layer-1 split (4 launches)
    k_detect<<<1, 256>>>(ei);
    k_edges_split<<<(NE + NN * DI + 255) / 256, 256>>>(ei, x, s_ahi, s_alo, NN * DI);
    k_scan<<<1, 1024>>>();
    k_scatter<<<(NE + 255) / 256, 256>>>();

    gat_layer(DI, Wl1, Wr1, at1, b1, xlr);
    gat_layer(DE, Wl2, Wr2, at2, b2, xlr);
    gat_layer(DE, Wl3, Wr3, at3, b3, xlr);

    // MLP: gemm1 fuses bias+leaky+split; gemm2 fuses bias+leaky+logit dot (no C write)
    prep_w(A1, nullptr, DE, DH, 1);
    run_gemm(s_ahi, s_alo, DE, DH, m1, c1, 3, s_bhi, s_blo, nullptr);
    prep_w(A2, nullptr, DH, DH, 1);
    run_gemm(s_bhi, s_blo, DH, DH, m1, c2, 1 | 4 | 8, nullptr, nullptr, A3);
    k_softmax<<<1, 1024>>>(out);
}